// round 5
// baseline (speedup 1.0000x reference)
#include <cuda_runtime.h>

#define NANCH 8732
#define NCLS  599
#define MC    300
#define CAP   4096
#define ROWD  604

typedef unsigned int u32;
typedef unsigned long long u64;

// ------------------- static device scratch (no allocations) -------------------
__device__ float g_scoresT[2u * NCLS * NANCH];   // [B, C, N] transposed scores
__device__ u32   g_clsmax[2 * NCLS];             // per-class max score bits
__device__ u64   g_tkey[2];                      // global cutoff key per image
__device__ u64   g_key[2 * CAP];                 // compacted kept keys
__device__ u32   g_aux[2 * CAP];                 // anchor ids parallel to g_key
__device__ u32   g_cnt[2];                       // per-image append counters

// ------------------------------- reset ---------------------------------------
__global__ void k_reset() {
    int t = blockIdx.x * blockDim.x + threadIdx.x;
    if (t < 2) g_cnt[t] = 0;
    if (t < 2 * NCLS) g_clsmax[t] = 0;
}

// ------------- fused transpose + per-class max (all coalesced) ---------------
// block: 32 anchors x all classes (chunks of 64), 256 threads
__global__ void __launch_bounds__(256) k_prep(const float* __restrict__ in) {
    __shared__ float t[32][65];
    int b  = blockIdx.y;
    int n0 = blockIdx.x * 32;
    int tid = threadIdx.x, lane = tid & 31, w = tid >> 5;   // 8 warps

    for (int c0 = 0; c0 < NCLS; c0 += 64) {
        // load 32 anchor-rows x 64 classes (coalesced 128B per access)
        #pragma unroll
        for (int r = 0; r < 4; r++) {
            int row = w * 4 + r;
            int n = n0 + row;
            float v0 = 0.f, v1 = 0.f;
            if (n < NANCH) {
                const float* src = in + ((size_t)b * NANCH + n) * ROWD + 1 + c0;
                if (c0 + lane < NCLS)      v0 = __ldg(&src[lane]);
                if (c0 + 32 + lane < NCLS) v1 = __ldg(&src[32 + lane]);
            }
            t[row][lane]      = v0;
            t[row][lane + 32] = v1;
        }
        __syncthreads();
        // store transposed: warp w -> class c0 + s*8 + w; lanes span anchors
        #pragma unroll
        for (int s = 0; s < 8; s++) {
            int cl  = s * 8 + w;
            int cgl = c0 + cl;
            int n   = n0 + lane;
            float v = t[lane][cl];                 // stride 65: conflict-free
            if (cgl < NCLS && n < NANCH)
                g_scoresT[((size_t)b * NCLS + cgl) * NANCH + n] = v;
            if (n >= NANCH) v = 0.f;
            #pragma unroll
            for (int off = 16; off; off >>= 1)
                v = fmaxf(v, __shfl_xor_sync(0xffffffffu, v, off));
            if (lane == 0 && cgl < NCLS)
                atomicMax(&g_clsmax[b * NCLS + cgl], __float_as_uint(v));
        }
        __syncthreads();
    }
}

// ------------- per-image cutoff = 200th largest class-max key ----------------
__global__ void k_thresh() {
    __shared__ u64 a[1024];
    int b = blockIdx.x, t = threadIdx.x;
    u64 v = 0;
    if (t < NCLS) {
        u32 mb = g_clsmax[b * NCLS + t];
        if (__uint_as_float(mb) > 0.01f)
            v = ((u64)mb << 32) | (u32)(~(u32)(t * MC));
    }
    a[t] = v;
    __syncthreads();
    for (int k = 2; k <= 1024; k <<= 1)
        for (int j = k >> 1; j; j >>= 1) {
            int i = t, x = i ^ j;
            if (x > i) {
                u64 p = a[i], q = a[x];
                bool sw = ((i & k) == 0) ? (p < q) : (p > q);
                if (sw) { a[i] = q; a[x] = p; }
            }
            __syncthreads();
        }
    if (t == 0) g_tkey[b] = a[199];
}

// -------- exact IoU>0.45 predicate with guarded div-free fast path -----------
__device__ __forceinline__ bool iou_gt(float y0, float x0, float y1, float x1, float a,
                                       float4 bj, float aj) {
    float ih = fmaxf(__fsub_rn(fminf(y1, bj.z), fmaxf(y0, bj.x)), 0.f);
    float iw = fmaxf(__fsub_rn(fminf(x1, bj.w), fmaxf(x0, bj.y)), 0.f);
    float inter = __fmul_rn(ih, iw);
    float uni   = __fsub_rn(__fadd_rn(a, aj), inter);
    if (!(uni > 0.f)) return false;
    float t = __fmul_rn(uni, 0.45f);
    if (inter > __fmul_rn(t, 1.000002f)) return true;
    if (inter < __fmul_rn(t, 0.999998f)) return false;
    return __fdiv_rn(inter, uni) > 0.45f;
}

// --------------- per-(b,c): top-300 select, NMS, filtered append --------------
__global__ void __launch_bounds__(512, 4) k_perclass(const float* __restrict__ in) {
    __shared__ __align__(16) char buf[9216 * 4];   // scores, later aliased by NMS state
    __shared__ u32 hist[256], suf[256], wtot[8];
    __shared__ u64 cand[512];
    __shared__ float4 tbox[32];
    __shared__ float  tarea[32];
    __shared__ u32    tsup[32];
    __shared__ u32    wcnt[16];
    __shared__ u32 s_cnt, s_cut, s_ge, s_above, s_kmask;
    __shared__ u64 s_tkey;

    int c = blockIdx.x, b = blockIdx.y;
    int tid = threadIdx.x, lane = tid & 31, wid = tid >> 5;

    u32* ssc = (u32*)buf;
    const float* sc = &g_scoresT[((size_t)b * NCLS + c) * NANCH];

    // ---- stage masked score bits (coalesced from transposed array) ----
    #pragma unroll
    for (int e = 0; e < 18; e++) {
        int i = e * 512 + tid;
        u32 v = 0;
        if (i < NANCH) {
            float s = __ldg(&sc[i]);
            v = (s > 0.01f) ? __float_as_uint(s) : 0u;
        }
        ssc[i] = v;
    }
    if (tid == 0) { s_cnt = 0; s_tkey = g_tkey[b]; }

    // ---- radix select, early exit when superset fits in 512 ----
    u32 prefix = 0, remain = MC, thresh = 0;
    for (int pass = 0; pass < 4; pass++) {
        int shift = 24 - 8 * pass;
        if (tid < 256) hist[tid] = 0;
        __syncthreads();
        #pragma unroll
        for (int e = 0; e < 18; e++) {
            u32 u = ssc[e * 512 + tid];
            bool part = (pass == 0) || ((u >> (shift + 8)) == prefix);
            int bin = (u >> shift) & 0xFF;
            int key = part ? bin : 999;
            u32 grp = __match_any_sync(0xffffffffu, key);
            if (part && lane == (u32)(__ffs(grp) - 1))
                atomicAdd(&hist[bin], __popc(grp));
        }
        __syncthreads();
        // warp-shuffle suffix scan over 256 bins (bins ascend with tid)
        if (tid < 256) {
            u32 v = hist[tid];
            #pragma unroll
            for (int off = 1; off < 32; off <<= 1) {
                u32 o = __shfl_down_sync(0xffffffffu, v, off);
                if (lane + off < 32) v += o;
            }
            if (lane == 0) wtot[wid] = v;       // wid in 0..7 here
            suf[tid] = v;                        // within-warp suffix, fixed next
        }
        __syncthreads();
        if (tid < 256) {
            u32 add = 0;
            #pragma unroll
            for (int w2 = 0; w2 < 8; w2++)
                if (w2 > wid) add += wtot[w2];
            suf[tid] += add;
        }
        if (tid == 0) { s_cut = 0; s_ge = 0; s_above = 0; }
        __syncthreads();
        if (tid == 0 && suf[0] < remain) s_ge = suf[0];   // shortfall default
        if (tid < 256) {
            u32 ge = suf[tid];
            u32 ab = (tid == 255) ? 0u : suf[tid + 1];
            if (ge >= remain && ab < remain) { s_cut = (u32)tid; s_ge = ge; s_above = ab; }
        }
        __syncthreads();
        u32 total_ge = (MC - remain) + s_ge;
        thresh = ((prefix << 8) | s_cut) << shift;
        if (total_ge <= 512 || pass == 3) break;
        prefix = (prefix << 8) | s_cut;
        remain -= s_above;
        __syncthreads();
    }

    // ---- collect superset, key = (score_bits<<32) | ~anchor ----
    #pragma unroll
    for (int e = 0; e < 18; e++) {
        u32 u = ssc[e * 512 + tid];
        if (u >= thresh && u != 0) {
            u32 pos = atomicAdd(&s_cnt, 1);
            if (pos < 512)
                cand[pos] = ((u64)u << 32) | (u32)(~(u32)(e * 512 + tid));
        }
    }
    __syncthreads();
    u32 cnt = min(s_cnt, 512u);
    if ((u32)tid >= cnt) cand[tid] = 0;
    __syncthreads();

    // ---- hybrid bitonic sort 512 desc: shfl for j<=16, smem for j>=32 ----
    {
        u64 p = cand[tid];
        #pragma unroll
        for (int k = 2; k <= 32; k <<= 1)
            #pragma unroll
            for (int j = k >> 1; j; j >>= 1) {
                u64 q = __shfl_xor_sync(0xffffffffu, p, j);
                bool keep_max = ((tid & k) == 0) == ((tid & j) == 0);
                p = keep_max ? (p > q ? p : q) : (p < q ? p : q);
            }
        cand[tid] = p;
        __syncthreads();
        for (int k = 64; k <= 512; k <<= 1) {
            for (int j = k >> 1; j >= 32; j >>= 1) {
                int i = tid, x = i ^ j;
                if (x > i) {
                    u64 a2 = cand[i], b2 = cand[x];
                    bool sw = ((i & k) == 0) ? (a2 < b2) : (a2 > b2);
                    if (sw) { cand[i] = b2; cand[x] = a2; }
                }
                __syncthreads();
            }
            p = cand[tid];
            #pragma unroll
            for (int j = 16; j; j >>= 1) {
                u64 q = __shfl_xor_sync(0xffffffffu, p, j);
                bool keep_max = ((tid & k) == 0) == ((tid & j) == 0);
                p = keep_max ? (p > q ? p : q) : (p < q ? p : q);
            }
            cand[tid] = p;
            __syncthreads();
        }
    }
    int M = min((int)cnt, MC);

    // ---- NMS state aliases dead score buffer ----
    float4* stb = (float4*)buf;                 // [320] compaction boxes
    float*  sta = (float*)(buf + 5120);         // [320] areas
    u32*    stp = (u32*)(buf + 6400);           // [320] original sorted rank
    u32*    smu = (u32*)(buf + 7680);           // [320] score bits by rank (fixed)
    u32*    smn = (u32*)(buf + 8960);           // [320] anchor by rank (fixed)

    float y0i = 0, x0i = 0, y1i = 0, x1i = 0, ai = 0;
    u32 pos = (u32)tid;
    bool alive = tid < M;
    if (alive) {
        u64 key = cand[tid];
        u32 ub = (u32)(key >> 32);
        u32 an = ~(u32)key;
        smu[tid] = ub;
        smn[tid] = an;
        const float4 bx = *(const float4*)(in + ((size_t)b * NANCH + an) * ROWD + 600);
        // bx = (cx, cy, w, h) -> exact reference corner encode
        y0i = __fsub_rn(bx.y, __fmul_rn(bx.w, 0.5f));
        x0i = __fsub_rn(bx.x, __fmul_rn(bx.z, 0.5f));
        y1i = __fadd_rn(bx.y, __fmul_rn(bx.w, 0.5f));
        x1i = __fadd_rn(bx.x, __fmul_rn(bx.z, 0.5f));
        ai  = __fmul_rn(__fsub_rn(y1i, y0i), __fsub_rn(x1i, x0i));
    }

    // ---- compacted tile-greedy NMS: alive candidates always occupy tid 0..total-1 ----
    int total = M;
    while (total > 0) {
        int nt = min(total, 32);
        if (tid < nt) { tbox[tid] = make_float4(y0i, x0i, y1i, x1i); tarea[tid] = ai; }
        __syncthreads();
        u32 msup = 0;
        if (alive) {
            int jm = (tid < nt) ? tid : nt;
            for (int j = 0; j < jm; j++)
                msup |= ((u32)iou_gt(y0i, x0i, y1i, x1i, ai, tbox[j], tarea[j])) << j;
        }
        if (tid < nt) tsup[tid] = msup;
        __syncthreads();
        if (tid == 0) {
            u32 km = 0;
            for (int k2 = 0; k2 < nt; k2++)
                if ((tsup[k2] & km) == 0u) km |= 1u << k2;
            s_kmask = km;
        }
        __syncthreads();
        u32 km = s_kmask;
        if (alive) {
            if (tid < nt) {
                if ((km >> tid) & 1u) {
                    u64 gkey = ((u64)smu[pos] << 32) | (u32)(~(u32)(c * MC + pos));
                    if (gkey >= s_tkey) {
                        u32 p2 = atomicAdd(&g_cnt[b], 1u);
                        if (p2 < CAP) { g_key[b * CAP + p2] = gkey; g_aux[b * CAP + p2] = smn[pos]; }
                    }
                }
                alive = false;                    // tile members finalized
            } else if (msup & km) {
                alive = false;                    // suppressed by a kept tile member
            }
        }
        // compact survivors to thread front (preserves sorted order)
        u32 wb = __ballot_sync(0xffffffffu, alive);
        if (lane == 0) wcnt[wid] = wb;
        __syncthreads();
        int newtotal = 0, before = 0;
        #pragma unroll
        for (int w2 = 0; w2 < 16; w2++) {
            int p2 = __popc(wcnt[w2]);
            newtotal += p2;
            if (w2 < wid) before += p2;
        }
        if (alive) {
            int r = before + __popc(wb & ((1u << lane) - 1u));
            stb[r] = make_float4(y0i, x0i, y1i, x1i);
            sta[r] = ai;
            stp[r] = pos;
        }
        __syncthreads();
        alive = tid < newtotal;
        if (alive) {
            float4 bx = stb[tid];
            y0i = bx.x; x0i = bx.y; y1i = bx.z; x1i = bx.w;
            ai = sta[tid]; pos = stp[tid];
        }
        total = newtotal;
        __syncthreads();
    }
}

// --------------------- final: top-200 by key, re-encode ----------------------
__global__ void __launch_bounds__(1024, 1) k_final(const float* __restrict__ in,
                                                   float* __restrict__ out) {
    __shared__ u64 skey[2048];
    __shared__ u32 saux[2048];
    int b = blockIdx.x, t = threadIdx.x;
    u32 n = min(min(g_cnt[b], (u32)CAP), 2048u);
    #pragma unroll
    for (int r = 0; r < 2; r++) {
        int i = t + r * 1024;
        if ((u32)i < n) { skey[i] = g_key[b * CAP + i]; saux[i] = g_aux[b * CAP + i]; }
        else            { skey[i] = 0;                  saux[i] = 0; }
    }
    __syncthreads();
    for (int k = 2; k <= 2048; k <<= 1)
        for (int j = k >> 1; j; j >>= 1) {
            #pragma unroll
            for (int r = 0; r < 2; r++) {
                int i = t + r * 1024, x = i ^ j;
                if (x > i) {
                    u64 p = skey[i], q = skey[x];
                    bool sw = ((i & k) == 0) ? (p < q) : (p > q);
                    if (sw) {
                        skey[i] = q; skey[x] = p;
                        u32 ap = saux[i]; saux[i] = saux[x]; saux[x] = ap;
                    }
                }
            }
            __syncthreads();
        }

    if (t < 200) {
        u64 key = skey[t];
        float cls = 0.f, score = 0.f, ocx = 0.f, ocy = 0.f, otw = 0.f, oth = 0.f;
        if (key) {
            score = __uint_as_float((u32)(key >> 32));
            u32 flat = ~(u32)key;
            cls = (float)(flat / MC + 1);
            u32 anchor = saux[t];
            const float4 bx = *(const float4*)(in + ((size_t)b * NANCH + anchor) * ROWD + 600);
            float y0 = __fsub_rn(bx.y, __fmul_rn(bx.w, 0.5f));
            float x0 = __fsub_rn(bx.x, __fmul_rn(bx.z, 0.5f));
            float y1 = __fadd_rn(bx.y, __fmul_rn(bx.w, 0.5f));
            float x1 = __fadd_rn(bx.x, __fmul_rn(bx.z, 0.5f));
            otw = __fsub_rn(x1, x0);
            oth = __fsub_rn(y1, y0);
            ocx = __fadd_rn(x0, __fmul_rn(otw, 0.5f));
            ocy = __fadd_rn(y0, __fmul_rn(oth, 0.5f));
        }
        float* o = out + ((size_t)b * 200 + t) * 6;
        o[0] = cls; o[1] = score; o[2] = ocx; o[3] = ocy; o[4] = otw; o[5] = oth;
    }
}

// ------------------------------------------------------------------------------
extern "C" void kernel_launch(void* const* d_in, const int* in_sizes, int n_in,
                              void* d_out, int out_size) {
    const float* in = (const float*)d_in[0];
    float* out = (float*)d_out;

    k_reset<<<2, 1024>>>();
    k_prep<<<dim3((NANCH + 31) / 32, 2), 256>>>(in);
    k_thresh<<<2, 1024>>>();
    k_perclass<<<dim3(NCLS, 2), 512>>>(in);
    k_final<<<2, 1024>>>(in, out);
}

// round 6
// speedup vs baseline: 1.0745x; 1.0745x over previous
#include <cuda_runtime.h>

#define NANCH 8732
#define NCLS  599
#define MC    300
#define CAP   4096
#define ROWD  604

typedef unsigned int u32;
typedef unsigned long long u64;

// ------------------- static device scratch (no allocations) -------------------
__device__ u32   g_sbits[2u * NCLS * NANCH];     // [B, C, N] masked score bits
__device__ u32   g_clsmax[2 * NCLS];             // per-class max score bits
__device__ u64   g_tkey[2];                      // global cutoff key per image
__device__ u64   g_key[2 * CAP];                 // compacted kept keys
__device__ u32   g_aux[2 * CAP];                 // anchor ids parallel to g_key
__device__ u32   g_cnt[2];                       // per-image append counters

// ------------------------------- reset ---------------------------------------
__global__ void k_reset() {
    int t = blockIdx.x * blockDim.x + threadIdx.x;
    if (t < 2) g_cnt[t] = 0;
    if (t < 2 * NCLS) g_clsmax[t] = 0;
}

// ---- streaming transpose: 64 anchors x 64 classes per CTA, masked bits out ----
__global__ void __launch_bounds__(512) k_prep(const float* __restrict__ in) {
    __shared__ float t[64][65];
    int b  = blockIdx.z;
    int n0 = blockIdx.x * 64;
    int c0 = blockIdx.y * 64;
    int tid = threadIdx.x, lane = tid & 31, w = tid >> 5;   // 16 warps

    // load 64 rows x 64 classes; warp w loads rows w*4..w*4+3, 8 loads in flight
    #pragma unroll
    for (int r = 0; r < 4; r++) {
        int row = w * 4 + r;
        int n = n0 + row;
        float v0 = 0.f, v1 = 0.f;
        if (n < NANCH) {
            const float* src = in + ((size_t)b * NANCH + n) * ROWD + 1 + c0;
            if (c0 + lane < NCLS)      v0 = __ldg(&src[lane]);
            if (c0 + 32 + lane < NCLS) v1 = __ldg(&src[32 + lane]);
        }
        t[row][lane]      = v0;
        t[row][lane + 32] = v1;
    }
    __syncthreads();

    // store transposed: warp w -> classes s*16+w; lanes span 64 anchors
    #pragma unroll
    for (int s = 0; s < 4; s++) {
        int cl  = s * 16 + w;
        int cgl = c0 + cl;
        float v0 = t[lane][cl];          // stride 65: conflict-free
        float v1 = t[lane + 32][cl];
        if (cgl < NCLS) {
            u32* dst = g_sbits + ((size_t)b * NCLS + cgl) * NANCH + n0;
            if (n0 + lane < NANCH)
                dst[lane]      = (v0 > 0.01f) ? __float_as_uint(v0) : 0u;
            if (n0 + 32 + lane < NANCH)
                dst[lane + 32] = (v1 > 0.01f) ? __float_as_uint(v1) : 0u;
        }
        float mx = fmaxf(v0, v1);        // OOB lanes loaded 0
        #pragma unroll
        for (int off = 16; off; off >>= 1)
            mx = fmaxf(mx, __shfl_xor_sync(0xffffffffu, mx, off));
        if (lane == 0 && cgl < NCLS)
            atomicMax(&g_clsmax[b * NCLS + cgl], __float_as_uint(mx));
    }
}

// ------------- per-image cutoff = 200th largest class-max key ----------------
__global__ void k_thresh() {
    __shared__ u64 a[1024];
    int b = blockIdx.x, t = threadIdx.x;
    u64 v = 0;
    if (t < NCLS) {
        u32 mb = g_clsmax[b * NCLS + t];
        if (__uint_as_float(mb) > 0.01f)
            v = ((u64)mb << 32) | (u32)(~(u32)(t * MC));
    }
    a[t] = v;
    __syncthreads();
    for (int k = 2; k <= 1024; k <<= 1)
        for (int j = k >> 1; j; j >>= 1) {
            int i = t, x = i ^ j;
            if (x > i) {
                u64 p = a[i], q = a[x];
                bool sw = ((i & k) == 0) ? (p < q) : (p > q);
                if (sw) { a[i] = q; a[x] = p; }
            }
            __syncthreads();
        }
    if (t == 0) g_tkey[b] = a[199];
}

// -------- exact IoU>0.45 predicate with guarded div-free fast path -----------
__device__ __forceinline__ bool iou_gt(float y0, float x0, float y1, float x1, float a,
                                       float4 bj, float aj) {
    float ih = fmaxf(__fsub_rn(fminf(y1, bj.z), fmaxf(y0, bj.x)), 0.f);
    float iw = fmaxf(__fsub_rn(fminf(x1, bj.w), fmaxf(x0, bj.y)), 0.f);
    float inter = __fmul_rn(ih, iw);
    float uni   = __fsub_rn(__fadd_rn(a, aj), inter);
    if (!(uni > 0.f)) return false;
    float t = __fmul_rn(uni, 0.45f);
    if (inter > __fmul_rn(t, 1.000002f)) return true;
    if (inter < __fmul_rn(t, 0.999998f)) return false;
    return __fdiv_rn(inter, uni) > 0.45f;
}

// --------------- per-(b,c): top-300 select, NMS, filtered append --------------
__global__ void __launch_bounds__(512, 4) k_perclass(const float* __restrict__ in) {
    __shared__ __align__(16) char buf[9216 * 4];   // score bits, later NMS state
    __shared__ u32 hist[256], suf[256], wtot[8];
    __shared__ u64 cand[512];
    __shared__ float4 tbox[64];
    __shared__ float  tarea[64];
    __shared__ u64    tsup[64];
    __shared__ u32    wcnt[16];
    __shared__ u32 s_cnt, s_cut, s_ge, s_above;
    __shared__ u64 s_tkey, s_kmask;

    int c = blockIdx.x, b = blockIdx.y;
    int tid = threadIdx.x, lane = tid & 31, wid = tid >> 5;

    u32* ssc = (u32*)buf;
    const u32* sb = &g_sbits[((size_t)b * NCLS + c) * NANCH];

    if (tid < 256) hist[tid] = 0;
    if (tid == 0) { s_cnt = 0; s_tkey = g_tkey[b]; }
    __syncthreads();

    // ---- fused stage + radix pass-0 histogram ----
    #pragma unroll
    for (int e = 0; e < 18; e++) {
        int i = e * 512 + tid;
        u32 v = (i < NANCH) ? __ldg(&sb[i]) : 0u;
        ssc[i] = v;
        int bin = v >> 24;
        u32 grp = __match_any_sync(0xffffffffu, bin);
        if (lane == (u32)(__ffs(grp) - 1))
            atomicAdd(&hist[bin], __popc(grp));
    }
    __syncthreads();

    // ---- radix select, early exit when superset fits in 512 ----
    u32 prefix = 0, remain = MC, thresh = 0;
    for (int pass = 0; pass < 4; pass++) {
        int shift = 24 - 8 * pass;
        if (pass > 0) {
            if (tid < 256) hist[tid] = 0;
            __syncthreads();
            #pragma unroll
            for (int e = 0; e < 18; e++) {
                u32 u = ssc[e * 512 + tid];
                bool part = (u >> (shift + 8)) == prefix;
                int bin = (u >> shift) & 0xFF;
                int key = part ? bin : 999;
                u32 grp = __match_any_sync(0xffffffffu, key);
                if (part && lane == (u32)(__ffs(grp) - 1))
                    atomicAdd(&hist[bin], __popc(grp));
            }
            __syncthreads();
        }
        // warp-shuffle suffix scan over 256 bins
        if (tid < 256) {
            u32 v = hist[tid];
            #pragma unroll
            for (int off = 1; off < 32; off <<= 1) {
                u32 o = __shfl_down_sync(0xffffffffu, v, off);
                if (lane + off < 32) v += o;
            }
            if (lane == 0) wtot[wid] = v;
            suf[tid] = v;
        }
        __syncthreads();
        if (tid < 256) {
            u32 add = 0;
            #pragma unroll
            for (int w2 = 0; w2 < 8; w2++)
                if (w2 > wid) add += wtot[w2];
            suf[tid] += add;
        }
        if (tid == 0) { s_cut = 0; s_ge = 0; s_above = 0; }
        __syncthreads();
        if (tid == 0 && suf[0] < remain) s_ge = suf[0];   // shortfall default
        if (tid < 256) {
            u32 ge = suf[tid];
            u32 ab = (tid == 255) ? 0u : suf[tid + 1];
            if (ge >= remain && ab < remain) { s_cut = (u32)tid; s_ge = ge; s_above = ab; }
        }
        __syncthreads();
        u32 total_ge = (MC - remain) + s_ge;
        thresh = ((prefix << 8) | s_cut) << shift;
        if (total_ge <= 512 || pass == 3) break;
        prefix = (prefix << 8) | s_cut;
        remain -= s_above;
        __syncthreads();
    }

    // ---- collect superset, key = (score_bits<<32) | ~anchor ----
    #pragma unroll
    for (int e = 0; e < 18; e++) {
        u32 u = ssc[e * 512 + tid];
        if (u >= thresh && u != 0) {
            u32 pos = atomicAdd(&s_cnt, 1);
            if (pos < 512)
                cand[pos] = ((u64)u << 32) | (u32)(~(u32)(e * 512 + tid));
        }
    }
    __syncthreads();
    u32 cnt = min(s_cnt, 512u);
    if ((u32)tid >= cnt) cand[tid] = 0;
    __syncthreads();

    // ---- hybrid bitonic sort 512 desc: shfl for j<=16, smem for j>=32 ----
    {
        u64 p = cand[tid];
        #pragma unroll
        for (int k = 2; k <= 32; k <<= 1)
            #pragma unroll
            for (int j = k >> 1; j; j >>= 1) {
                u64 q = __shfl_xor_sync(0xffffffffu, p, j);
                bool keep_max = ((tid & k) == 0) == ((tid & j) == 0);
                p = keep_max ? (p > q ? p : q) : (p < q ? p : q);
            }
        cand[tid] = p;
        __syncthreads();
        for (int k = 64; k <= 512; k <<= 1) {
            for (int j = k >> 1; j >= 32; j >>= 1) {
                int i = tid, x = i ^ j;
                if (x > i) {
                    u64 a2 = cand[i], b2 = cand[x];
                    bool sw = ((i & k) == 0) ? (a2 < b2) : (a2 > b2);
                    if (sw) { cand[i] = b2; cand[x] = a2; }
                }
                __syncthreads();
            }
            p = cand[tid];
            #pragma unroll
            for (int j = 16; j; j >>= 1) {
                u64 q = __shfl_xor_sync(0xffffffffu, p, j);
                bool keep_max = ((tid & k) == 0) == ((tid & j) == 0);
                p = keep_max ? (p > q ? p : q) : (p < q ? p : q);
            }
            cand[tid] = p;
            __syncthreads();
        }
    }
    int M = min((int)cnt, MC);

    // ---- NMS state aliases dead score buffer ----
    float4* stb = (float4*)buf;                 // [320] compaction boxes
    float*  sta = (float*)(buf + 5120);         // [320] areas
    u32*    stp = (u32*)(buf + 6400);           // [320] original sorted rank
    u32*    smu = (u32*)(buf + 7680);           // [320] score bits by rank (fixed)
    u32*    smn = (u32*)(buf + 8960);           // [320] anchor by rank (fixed)

    float y0i = 0, x0i = 0, y1i = 0, x1i = 0, ai = 0;
    u32 pos = (u32)tid;
    bool alive = tid < M;
    if (alive) {
        u64 key = cand[tid];
        u32 ub = (u32)(key >> 32);
        u32 an = ~(u32)key;
        smu[tid] = ub;
        smn[tid] = an;
        const float4 bx = *(const float4*)(in + ((size_t)b * NANCH + an) * ROWD + 600);
        // bx = (cx, cy, w, h) -> exact reference corner encode
        y0i = __fsub_rn(bx.y, __fmul_rn(bx.w, 0.5f));
        x0i = __fsub_rn(bx.x, __fmul_rn(bx.z, 0.5f));
        y1i = __fadd_rn(bx.y, __fmul_rn(bx.w, 0.5f));
        x1i = __fadd_rn(bx.x, __fmul_rn(bx.z, 0.5f));
        ai  = __fmul_rn(__fsub_rn(y1i, y0i), __fsub_rn(x1i, x0i));
    }

    // ---- compacted tile-greedy NMS, 64 candidates finalized per round ----
    int total = M;
    while (total > 0) {
        int nt = min(total, 64);
        if (tid < nt) { tbox[tid] = make_float4(y0i, x0i, y1i, x1i); tarea[tid] = ai; }
        __syncthreads();
        u64 msup = 0;
        if (alive) {
            int jm = (tid < nt) ? tid : nt;
            for (int j = 0; j < jm; j++)
                msup |= ((u64)iou_gt(y0i, x0i, y1i, x1i, ai, tbox[j], tarea[j])) << j;
        }
        if (tid < nt) tsup[tid] = msup;
        __syncthreads();
        if (tid == 0) {
            u64 km = 0;
            for (int k2 = 0; k2 < nt; k2++)
                if ((tsup[k2] & km) == 0ull) km |= 1ull << k2;
            s_kmask = km;
        }
        __syncthreads();
        u64 km = s_kmask;
        if (alive) {
            if (tid < nt) {
                if ((km >> tid) & 1ull) {
                    u64 gkey = ((u64)smu[pos] << 32) | (u32)(~(u32)(c * MC + pos));
                    if (gkey >= s_tkey) {
                        u32 p2 = atomicAdd(&g_cnt[b], 1u);
                        if (p2 < CAP) { g_key[b * CAP + p2] = gkey; g_aux[b * CAP + p2] = smn[pos]; }
                    }
                }
                alive = false;                    // tile members finalized
            } else if (msup & km) {
                alive = false;                    // suppressed by a kept tile member
            }
        }
        // compact survivors to thread front (preserves sorted order)
        u32 wb = __ballot_sync(0xffffffffu, alive);
        if (lane == 0) wcnt[wid] = wb;
        __syncthreads();
        int newtotal = 0, before = 0;
        #pragma unroll
        for (int w2 = 0; w2 < 16; w2++) {
            int p2 = __popc(wcnt[w2]);
            newtotal += p2;
            if (w2 < wid) before += p2;
        }
        if (alive) {
            int r = before + __popc(wb & ((1u << lane) - 1u));
            stb[r] = make_float4(y0i, x0i, y1i, x1i);
            sta[r] = ai;
            stp[r] = pos;
        }
        __syncthreads();
        alive = tid < newtotal;
        if (alive) {
            float4 bx = stb[tid];
            y0i = bx.x; x0i = bx.y; y1i = bx.z; x1i = bx.w;
            ai = sta[tid]; pos = stp[tid];
        }
        total = newtotal;
        __syncthreads();
    }
}

// --------------------- final: top-200 by key, re-encode ----------------------
__global__ void __launch_bounds__(1024, 1) k_final(const float* __restrict__ in,
                                                   float* __restrict__ out) {
    __shared__ u64 skey[2048];
    __shared__ u32 saux[2048];
    int b = blockIdx.x, t = threadIdx.x;
    u32 n = min(min(g_cnt[b], (u32)CAP), 2048u);
    #pragma unroll
    for (int r = 0; r < 2; r++) {
        int i = t + r * 1024;
        if ((u32)i < n) { skey[i] = g_key[b * CAP + i]; saux[i] = g_aux[b * CAP + i]; }
        else            { skey[i] = 0;                  saux[i] = 0; }
    }
    __syncthreads();
    for (int k = 2; k <= 2048; k <<= 1)
        for (int j = k >> 1; j; j >>= 1) {
            #pragma unroll
            for (int r = 0; r < 2; r++) {
                int i = t + r * 1024, x = i ^ j;
                if (x > i) {
                    u64 p = skey[i], q = skey[x];
                    bool sw = ((i & k) == 0) ? (p < q) : (p > q);
                    if (sw) {
                        skey[i] = q; skey[x] = p;
                        u32 ap = saux[i]; saux[i] = saux[x]; saux[x] = ap;
                    }
                }
            }
            __syncthreads();
        }

    if (t < 200) {
        u64 key = skey[t];
        float cls = 0.f, score = 0.f, ocx = 0.f, ocy = 0.f, otw = 0.f, oth = 0.f;
        if (key) {
            score = __uint_as_float((u32)(key >> 32));
            u32 flat = ~(u32)key;
            cls = (float)(flat / MC + 1);
            u32 anchor = saux[t];
            const float4 bx = *(const float4*)(in + ((size_t)b * NANCH + anchor) * ROWD + 600);
            float y0 = __fsub_rn(bx.y, __fmul_rn(bx.w, 0.5f));
            float x0 = __fsub_rn(bx.x, __fmul_rn(bx.z, 0.5f));
            float y1 = __fadd_rn(bx.y, __fmul_rn(bx.w, 0.5f));
            float x1 = __fadd_rn(bx.x, __fmul_rn(bx.z, 0.5f));
            otw = __fsub_rn(x1, x0);
            oth = __fsub_rn(y1, y0);
            ocx = __fadd_rn(x0, __fmul_rn(otw, 0.5f));
            ocy = __fadd_rn(y0, __fmul_rn(oth, 0.5f));
        }
        float* o = out + ((size_t)b * 200 + t) * 6;
        o[0] = cls; o[1] = score; o[2] = ocx; o[3] = ocy; o[4] = otw; o[5] = oth;
    }
}

// ------------------------------------------------------------------------------
extern "C" void kernel_launch(void* const* d_in, const int* in_sizes, int n_in,
                              void* d_out, int out_size) {
    const float* in = (const float*)d_in[0];
    float* out = (float*)d_out;

    k_reset<<<2, 1024>>>();
    k_prep<<<dim3((NANCH + 63) / 64, (NCLS + 63) / 64, 2), 512>>>(in);
    k_thresh<<<2, 1024>>>();
    k_perclass<<<dim3(NCLS, 2), 512>>>(in);
    k_final<<<2, 1024>>>(in, out);
}